// round 1
// baseline (speedup 1.0000x reference)
#include <cuda_runtime.h>
#include <math.h>

#define D     768
#define SEQ   4096
#define BATCH 4

// Scratch (device globals — no allocation allowed in kernel_launch)
__device__ float g_Q[BATCH * SEQ * D];                 // 48 MB
__device__ float g_K[BATCH * SEQ * D];                 // 48 MB
__device__ float g_V[BATCH * SEQ * D];                 // 48 MB
__device__ float g_S[(size_t)BATCH * SEQ * SEQ];       // 256 MB (scores -> probs)

#define SCALE 0.03608439182435161f  // 1/sqrt(768)

// ---------------------------------------------------------------------------
// 128x128 fp32 tile GEMM (NT): C_tile += A[128,K] * B[128,K]^T
// A pre-offset to block row, B pre-offset to block col. K % 8 == 0.
// 256 threads, 8x8 per-thread microtile.
// ---------------------------------------------------------------------------
__device__ __forceinline__ void sgemm128_nt(
    const float* __restrict__ A, const float* __restrict__ B,
    int K, int lda, int ldb, float acc[8][8])
{
    __shared__ __align__(16) float As[8][128];
    __shared__ __align__(16) float Bs[8][128];

    const int tid  = threadIdx.x;
    const int arow = tid >> 1;          // 0..127
    const int acol = (tid & 1) * 4;     // 0 or 4
    const int tx   = tid & 15;
    const int ty   = tid >> 4;

    const float* Ap = A + (size_t)arow * lda + acol;
    const float* Bp = B + (size_t)arow * ldb + acol;

    for (int k0 = 0; k0 < K; k0 += 8) {
        float4 a4 = *(const float4*)(Ap + k0);
        float4 b4 = *(const float4*)(Bp + k0);
        __syncthreads();
        As[acol + 0][arow] = a4.x; As[acol + 1][arow] = a4.y;
        As[acol + 2][arow] = a4.z; As[acol + 3][arow] = a4.w;
        Bs[acol + 0][arow] = b4.x; Bs[acol + 1][arow] = b4.y;
        Bs[acol + 2][arow] = b4.z; Bs[acol + 3][arow] = b4.w;
        __syncthreads();
        #pragma unroll
        for (int k = 0; k < 8; k++) {
            float a[8], b[8];
            *(float4*)&a[0] = *(const float4*)&As[k][ty * 4];
            *(float4*)&a[4] = *(const float4*)&As[k][ty * 4 + 64];
            *(float4*)&b[0] = *(const float4*)&Bs[k][tx * 4];
            *(float4*)&b[4] = *(const float4*)&Bs[k][tx * 4 + 64];
            #pragma unroll
            for (int i = 0; i < 8; i++)
                #pragma unroll
                for (int j = 0; j < 8; j++)
                    acc[i][j] = fmaf(a[i], b[j], acc[i][j]);
        }
    }
}

// Write the 8x8 microtile (rows {ty*4..+3, +64..}, cols {tx*4..+3, +64..})
__device__ __forceinline__ void write_tile(
    float* __restrict__ C, int ldc, int row0, int col0,
    const float acc[8][8], float scale)
{
    const int tx = threadIdx.x & 15;
    const int ty = threadIdx.x >> 4;
    #pragma unroll
    for (int i = 0; i < 8; i++) {
        int r = row0 + ((i < 4) ? (ty * 4 + i) : (ty * 4 + 64 + i - 4));
        float4 lo = make_float4(acc[i][0]*scale, acc[i][1]*scale,
                                acc[i][2]*scale, acc[i][3]*scale);
        float4 hi = make_float4(acc[i][4]*scale, acc[i][5]*scale,
                                acc[i][6]*scale, acc[i][7]*scale);
        *(float4*)(C + (size_t)r * ldc + col0 + tx * 4)      = lo;
        *(float4*)(C + (size_t)r * ldc + col0 + tx * 4 + 64) = hi;
    }
}

// ---------------------------------------------------------------------------
// Kernel 1: QKV projection. z selects {Q,K,V}. C[16384,768] = X * W^T
// ---------------------------------------------------------------------------
__global__ void __launch_bounds__(256) qkv_kernel(
    const float* __restrict__ X,
    const float* __restrict__ Wq, const float* __restrict__ Wk,
    const float* __restrict__ Wv)
{
    const float* W = (blockIdx.z == 0) ? Wq : (blockIdx.z == 1) ? Wk : Wv;
    float*       O = (blockIdx.z == 0) ? g_Q : (blockIdx.z == 1) ? g_K : g_V;
    const int row0 = blockIdx.y * 128;
    const int col0 = blockIdx.x * 128;
    float acc[8][8] = {};
    sgemm128_nt(X + (size_t)row0 * D, W + (size_t)col0 * D, D, D, D, acc);
    write_tile(O, D, row0, col0, acc, 1.0f);
}

// ---------------------------------------------------------------------------
// Kernel 2: S = (Q K^T) * scale, lower-triangular tiles only.
// Upper-triangle garbage is never read (softmax reads k<=q only).
// ---------------------------------------------------------------------------
__global__ void __launch_bounds__(256) scores_kernel()
{
    if (blockIdx.x > blockIdx.y) return;   // strictly-above-diagonal tile
    const int b    = blockIdx.z;
    const int row0 = blockIdx.y * 128;     // q
    const int col0 = blockIdx.x * 128;     // k
    const float* Qb = g_Q + (size_t)b * SEQ * D;
    const float* Kb = g_K + (size_t)b * SEQ * D;
    float*       Sb = g_S + (size_t)b * SEQ * SEQ;
    float acc[8][8] = {};
    sgemm128_nt(Qb + (size_t)row0 * D, Kb + (size_t)col0 * D, D, D, D, acc);
    write_tile(Sb, SEQ, row0, col0, acc, SCALE);
}

// ---------------------------------------------------------------------------
// Kernel 3: causal row softmax. Row q: reads cols [0,q], writes normalized
// probs and zero-fills up to the 128-aligned boundary ((q/128+1)*128) so the
// PV GEMM can consume whole 128-wide K-blocks without masking.
// ---------------------------------------------------------------------------
__global__ void __launch_bounds__(256) softmax_kernel()
{
    const int q = blockIdx.x;
    const int b = blockIdx.y;
    float* row = g_S + (size_t)b * SEQ * SEQ + (size_t)q * SEQ;
    const int len  = q + 1;
    const int wlen = ((q >> 7) + 1) << 7;
    const int tid  = threadIdx.x;
    __shared__ float red[256];

    float m = -INFINITY;
    for (int i = tid; i < len; i += 256) m = fmaxf(m, row[i]);
    red[tid] = m; __syncthreads();
    #pragma unroll
    for (int s = 128; s > 0; s >>= 1) {
        if (tid < s) red[tid] = fmaxf(red[tid], red[tid + s]);
        __syncthreads();
    }
    m = red[0]; __syncthreads();

    float sum = 0.0f;
    for (int i = tid; i < len; i += 256) {
        float e = __expf(row[i] - m);
        row[i] = e;
        sum += e;
    }
    red[tid] = sum; __syncthreads();
    #pragma unroll
    for (int s = 128; s > 0; s >>= 1) {
        if (tid < s) red[tid] += red[tid + s];
        __syncthreads();
    }
    const float inv = 1.0f / red[0];
    __syncthreads();

    for (int i = tid; i < wlen; i += 256)
        row[i] = (i < len) ? row[i] * inv : 0.0f;
}

// ---------------------------------------------------------------------------
// Kernel 4: O = P * V (NN GEMM), K limited to (block_row+1)*128 (causal).
// ---------------------------------------------------------------------------
__global__ void __launch_bounds__(256) pv_kernel(float* __restrict__ Out)
{
    const int b    = blockIdx.z;
    const int row0 = blockIdx.y * 128;
    const int col0 = blockIdx.x * 128;
    const int Klim = (blockIdx.y + 1) * 128;

    const float* P = g_S + (size_t)b * SEQ * SEQ;
    const float* V = g_V + (size_t)b * SEQ * D;
    float*       O = Out + (size_t)b * SEQ * D;

    __shared__ __align__(16) float As[8][128];
    __shared__ __align__(16) float Bs[8][128];

    const int tid  = threadIdx.x;
    const int arow = tid >> 1;
    const int acol = (tid & 1) * 4;
    const int brow = tid >> 5;          // 0..7
    const int bcol = (tid & 31) * 4;    // 0..124
    const int tx   = tid & 15;
    const int ty   = tid >> 4;

    float acc[8][8] = {};

    for (int k0 = 0; k0 < Klim; k0 += 8) {
        float4 a4 = *(const float4*)(P + (size_t)(row0 + arow) * SEQ + k0 + acol);
        float4 b4 = *(const float4*)(V + (size_t)(k0 + brow) * D + col0 + bcol);
        __syncthreads();
        As[acol + 0][arow] = a4.x; As[acol + 1][arow] = a4.y;
        As[acol + 2][arow] = a4.z; As[acol + 3][arow] = a4.w;
        *(float4*)&Bs[brow][bcol] = b4;
        __syncthreads();
        #pragma unroll
        for (int k = 0; k < 8; k++) {
            float a[8], bb[8];
            *(float4*)&a[0]  = *(const float4*)&As[k][ty * 4];
            *(float4*)&a[4]  = *(const float4*)&As[k][ty * 4 + 64];
            *(float4*)&bb[0] = *(const float4*)&Bs[k][tx * 4];
            *(float4*)&bb[4] = *(const float4*)&Bs[k][tx * 4 + 64];
            #pragma unroll
            for (int i = 0; i < 8; i++)
                #pragma unroll
                for (int j = 0; j < 8; j++)
                    acc[i][j] = fmaf(a[i], bb[j], acc[i][j]);
        }
    }
    write_tile(O, D, row0, col0, acc, 1.0f);
}

// ---------------------------------------------------------------------------
extern "C" void kernel_launch(void* const* d_in, const int* in_sizes, int n_in,
                              void* d_out, int out_size)
{
    const float* X  = (const float*)d_in[0];
    const float* Wq = (const float*)d_in[1];
    const float* Wk = (const float*)d_in[2];
    const float* Wv = (const float*)d_in[3];
    float* Out = (float*)d_out;

    // Q/K/V projections: M=16384, N=768, K=768, 3 weight matrices
    qkv_kernel<<<dim3(D / 128, (BATCH * SEQ) / 128, 3), 256>>>(X, Wq, Wk, Wv);
    // Scores: lower-triangular 128x128 tiles, scaled
    scores_kernel<<<dim3(SEQ / 128, SEQ / 128, BATCH), 256>>>();
    // Causal row softmax (zero-fills to 128-aligned boundary)
    softmax_kernel<<<dim3(SEQ, BATCH), 256>>>();
    // O = P V with causal K-limit
    pv_kernel<<<dim3(D / 128, SEQ / 128, BATCH), 256>>>(Out);
}

// round 2
// speedup vs baseline: 2.1671x; 2.1671x over previous
#include <cuda_runtime.h>
#include <cuda_bf16.h>
#include <math.h>
#include <stdint.h>

#define D     768
#define SEQ   4096
#define BATCH 4
#define SCALE 0.03608439182435161f  // 1/sqrt(768)

// Scratch (device globals — no allocation allowed in kernel_launch)
__device__ float g_Q[BATCH * SEQ * D];                 // 48 MB
__device__ float g_K[BATCH * SEQ * D];                 // 48 MB
__device__ float g_Vt[BATCH * (size_t)D * SEQ];        // 48 MB, [b][d][seq]
__device__ float g_S[(size_t)BATCH * SEQ * SEQ];       // 256 MB (scores -> probs)

#define LDS_STRIDE 40   // bf16 elements per smem row (80B -> conflict-free ldmatrix)

// ---------------------------------------------------------------------------
// PTX wrappers
// ---------------------------------------------------------------------------
__device__ __forceinline__ void ldsm4(uint32_t r[4], uint32_t addr) {
    asm volatile("ldmatrix.sync.aligned.m8n8.x4.shared.b16 {%0,%1,%2,%3}, [%4];"
                 : "=r"(r[0]), "=r"(r[1]), "=r"(r[2]), "=r"(r[3]) : "r"(addr));
}

__device__ __forceinline__ void mma16816(float c[4], const uint32_t a[4],
                                         uint32_t b0, uint32_t b1) {
    asm volatile(
        "mma.sync.aligned.m16n8k16.row.col.f32.bf16.bf16.f32 "
        "{%0,%1,%2,%3}, {%4,%5,%6,%7}, {%8,%9}, {%0,%1,%2,%3};"
        : "+f"(c[0]), "+f"(c[1]), "+f"(c[2]), "+f"(c[3])
        : "r"(a[0]), "r"(a[1]), "r"(a[2]), "r"(a[3]), "r"(b0), "r"(b1));
}

// ---------------------------------------------------------------------------
// Load a 128x32 fp32 tile from global, split each value into bf16 hi + lo,
// store to smem (stride LDS_STRIDE).  256 threads: each loads 16 floats.
// ---------------------------------------------------------------------------
__device__ __forceinline__ void load_tile_split(
    const float* __restrict__ src, int ld, int k0,
    __nv_bfloat16* __restrict__ hi, __nv_bfloat16* __restrict__ lo)
{
    const int t   = threadIdx.x;
    const int row = t >> 1;
    const int cg  = (t & 1) * 16;
    const float* p = src + (size_t)row * ld + k0 + cg;

    float v[16];
    *(float4*)&v[0]  = *(const float4*)(p + 0);
    *(float4*)&v[4]  = *(const float4*)(p + 4);
    *(float4*)&v[8]  = *(const float4*)(p + 8);
    *(float4*)&v[12] = *(const float4*)(p + 12);

    __nv_bfloat16* ph = hi + row * LDS_STRIDE + cg;
    __nv_bfloat16* pl = lo + row * LDS_STRIDE + cg;
    #pragma unroll
    for (int i = 0; i < 16; i += 2) {
        __nv_bfloat16 hx = __float2bfloat16_rn(v[i]);
        __nv_bfloat16 hy = __float2bfloat16_rn(v[i + 1]);
        __nv_bfloat16 lx = __float2bfloat16_rn(v[i]     - __bfloat162float(hx));
        __nv_bfloat16 ly = __float2bfloat16_rn(v[i + 1] - __bfloat162float(hy));
        *(__nv_bfloat162*)(ph + i) = __nv_bfloat162(hx, hy);
        *(__nv_bfloat162*)(pl + i) = __nv_bfloat162(lx, ly);
    }
}

// ---------------------------------------------------------------------------
// Core 128x128 GEMM (NT): C += A[128,K] * B[128,K]^T using bf16x3 mma.
// A, B pre-offset to block row/col.  K % 32 == 0.  256 threads.
// acc layout: acc[mtile(2)][ntile(8)][4]
// ---------------------------------------------------------------------------
__device__ __forceinline__ void gemm_core(
    const float* __restrict__ A, int lda,
    const float* __restrict__ B, int ldb,
    int K, float acc[2][8][4])
{
    __shared__ __align__(16) __nv_bfloat16 sAh[128 * LDS_STRIDE];
    __shared__ __align__(16) __nv_bfloat16 sAl[128 * LDS_STRIDE];
    __shared__ __align__(16) __nv_bfloat16 sBh[128 * LDS_STRIDE];
    __shared__ __align__(16) __nv_bfloat16 sBl[128 * LDS_STRIDE];

    const int tid  = threadIdx.x;
    const int lane = tid & 31;
    const int warp = tid >> 5;
    const int wm   = warp >> 1;   // 0..3 -> row offset wm*32
    const int wn   = warp & 1;    // 0..1 -> col offset wn*64

    const uint32_t bAh = (uint32_t)__cvta_generic_to_shared(sAh);
    const uint32_t bAl = (uint32_t)__cvta_generic_to_shared(sAl);
    const uint32_t bBh = (uint32_t)__cvta_generic_to_shared(sBh);
    const uint32_t bBl = (uint32_t)__cvta_generic_to_shared(sBl);

    // ldmatrix lane->address mapping
    const int rowA = ((lane >> 3) & 1) * 8 + (lane & 7);
    const int colA = (lane >> 4) * 8;
    const int rowB = (lane >> 4) * 8 + (lane & 7);
    const int colB = ((lane >> 3) & 1) * 8;

    uint32_t offA[2], offB[4];
    #pragma unroll
    for (int mt = 0; mt < 2; mt++)
        offA[mt] = ((wm * 32 + mt * 16 + rowA) * LDS_STRIDE + colA) * 2;
    #pragma unroll
    for (int g = 0; g < 4; g++)
        offB[g] = ((wn * 64 + g * 16 + rowB) * LDS_STRIDE + colB) * 2;

    for (int k0 = 0; k0 < K; k0 += 32) {
        __syncthreads();
        load_tile_split(A, lda, k0, sAh, sAl);
        load_tile_split(B, ldb, k0, sBh, sBl);
        __syncthreads();

        #pragma unroll
        for (int kk = 0; kk < 32; kk += 16) {
            uint32_t afh[2][4], afl[2][4];
            ldsm4(afh[0], bAh + offA[0] + kk * 2);
            ldsm4(afh[1], bAh + offA[1] + kk * 2);
            ldsm4(afl[0], bAl + offA[0] + kk * 2);
            ldsm4(afl[1], bAl + offA[1] + kk * 2);

            #pragma unroll
            for (int g = 0; g < 4; g++) {
                uint32_t bh[4], bl[4];
                ldsm4(bh, bBh + offB[g] + kk * 2);
                ldsm4(bl, bBl + offB[g] + kk * 2);
                #pragma unroll
                for (int mt = 0; mt < 2; mt++) {
                    #pragma unroll
                    for (int nt = 0; nt < 2; nt++) {
                        float* c = acc[mt][g * 2 + nt];
                        mma16816(c, afh[mt], bh[nt * 2], bh[nt * 2 + 1]); // hi*hi
                        mma16816(c, afh[mt], bl[nt * 2], bl[nt * 2 + 1]); // hi*lo
                        mma16816(c, afl[mt], bh[nt * 2], bh[nt * 2 + 1]); // lo*hi
                    }
                }
            }
        }
    }
}

// Standard (row-major) accumulator store, optional scale.
__device__ __forceinline__ void store_acc(
    float* __restrict__ C, size_t ldc, int row0, int col0,
    const float acc[2][8][4], float scale)
{
    const int lane = threadIdx.x & 31;
    const int warp = threadIdx.x >> 5;
    const int wm = warp >> 1, wn = warp & 1;
    #pragma unroll
    for (int mt = 0; mt < 2; mt++) {
        const int r = row0 + wm * 32 + mt * 16 + (lane >> 2);
        #pragma unroll
        for (int j = 0; j < 8; j++) {
            const int c = col0 + wn * 64 + j * 8 + (lane & 3) * 2;
            *(float2*)(C + (size_t)r * ldc + c) =
                make_float2(acc[mt][j][0] * scale, acc[mt][j][1] * scale);
            *(float2*)(C + (size_t)(r + 8) * ldc + c) =
                make_float2(acc[mt][j][2] * scale, acc[mt][j][3] * scale);
        }
    }
}

// Transposed store for V: element (r=seq, c=d) -> Vt[b][c][r % SEQ]
__device__ __forceinline__ void store_acc_T(
    float* __restrict__ Ct, size_t ldt, int row0, int col0,
    const float acc[2][8][4])
{
    const int lane = threadIdx.x & 31;
    const int warp = threadIdx.x >> 5;
    const int wm = warp >> 1, wn = warp & 1;
    #pragma unroll
    for (int mt = 0; mt < 2; mt++) {
        const int r = row0 + wm * 32 + mt * 16 + (lane >> 2);
        #pragma unroll
        for (int j = 0; j < 8; j++) {
            const int c = col0 + wn * 64 + j * 8 + (lane & 3) * 2;
            Ct[(size_t)c       * ldt + r]     = acc[mt][j][0];
            Ct[(size_t)(c + 1) * ldt + r]     = acc[mt][j][1];
            Ct[(size_t)c       * ldt + r + 8] = acc[mt][j][2];
            Ct[(size_t)(c + 1) * ldt + r + 8] = acc[mt][j][3];
        }
    }
}

// ---------------------------------------------------------------------------
// Kernel 1: QKV projection. z selects {Q,K,V}. V written transposed.
// ---------------------------------------------------------------------------
__global__ void __launch_bounds__(256) qkv_kernel(
    const float* __restrict__ X,
    const float* __restrict__ Wq, const float* __restrict__ Wk,
    const float* __restrict__ Wv)
{
    const float* W = (blockIdx.z == 0) ? Wq : (blockIdx.z == 1) ? Wk : Wv;
    const int row0 = blockIdx.y * 128;
    const int col0 = blockIdx.x * 128;

    float acc[2][8][4] = {};
    gemm_core(X + (size_t)row0 * D, D, W + (size_t)col0 * D, D, D, acc);

    if (blockIdx.z == 0) {
        store_acc(g_Q, D, row0, col0, acc, 1.0f);
    } else if (blockIdx.z == 1) {
        store_acc(g_K, D, row0, col0, acc, 1.0f);
    } else {
        const int b = row0 >> 12;                    // 4096 rows per batch
        float* Vt_b = g_Vt + (size_t)b * D * SEQ;
        store_acc_T(Vt_b, SEQ, row0 & (SEQ - 1), col0, acc);
    }
}

// ---------------------------------------------------------------------------
// Kernel 2: S = (Q K^T) * scale, lower-triangular tiles only.
// ---------------------------------------------------------------------------
__global__ void __launch_bounds__(256) scores_kernel()
{
    if (blockIdx.x > blockIdx.y) return;
    const int b    = blockIdx.z;
    const int row0 = blockIdx.y * 128;
    const int col0 = blockIdx.x * 128;
    const float* Qb = g_Q + (size_t)b * SEQ * D;
    const float* Kb = g_K + (size_t)b * SEQ * D;
    float*       Sb = g_S + (size_t)b * SEQ * SEQ;

    float acc[2][8][4] = {};
    gemm_core(Qb + (size_t)row0 * D, D, Kb + (size_t)col0 * D, D, D, acc);
    store_acc(Sb, SEQ, row0, col0, acc, SCALE);
}

// ---------------------------------------------------------------------------
// Kernel 3: causal row softmax, zero-fill to 128-aligned boundary.
// ---------------------------------------------------------------------------
__global__ void __launch_bounds__(256) softmax_kernel()
{
    const int q = blockIdx.x;
    const int b = blockIdx.y;
    float* row = g_S + (size_t)b * SEQ * SEQ + (size_t)q * SEQ;
    const int len  = q + 1;
    const int wlen = ((q >> 7) + 1) << 7;
    const int tid  = threadIdx.x;
    __shared__ float red[256];

    float m = -INFINITY;
    for (int i = tid; i < len; i += 256) m = fmaxf(m, row[i]);
    red[tid] = m; __syncthreads();
    #pragma unroll
    for (int s = 128; s > 0; s >>= 1) {
        if (tid < s) red[tid] = fmaxf(red[tid], red[tid + s]);
        __syncthreads();
    }
    m = red[0]; __syncthreads();

    float sum = 0.0f;
    for (int i = tid; i < len; i += 256) {
        float e = __expf(row[i] - m);
        row[i] = e;
        sum += e;
    }
    red[tid] = sum; __syncthreads();
    #pragma unroll
    for (int s = 128; s > 0; s >>= 1) {
        if (tid < s) red[tid] += red[tid + s];
        __syncthreads();
    }
    const float inv = 1.0f / red[0];
    __syncthreads();

    for (int i = tid; i < wlen; i += 256)
        row[i] = (i < len) ? row[i] * inv : 0.0f;
}

// ---------------------------------------------------------------------------
// Kernel 4: O = P * V using Vt (NT GEMM), causal K-limit.
// ---------------------------------------------------------------------------
__global__ void __launch_bounds__(256) pv_kernel(float* __restrict__ Out)
{
    const int b    = blockIdx.z;
    const int row0 = blockIdx.y * 128;
    const int col0 = blockIdx.x * 128;
    const int Klim = (blockIdx.y + 1) * 128;

    const float* P  = g_S  + (size_t)b * SEQ * SEQ;
    const float* Vt = g_Vt + (size_t)b * D * SEQ;
    float*       O  = Out  + (size_t)b * SEQ * D;

    float acc[2][8][4] = {};
    gemm_core(P + (size_t)row0 * SEQ, SEQ, Vt + (size_t)col0 * SEQ, SEQ, Klim, acc);
    store_acc(O, D, row0, col0, acc, 1.0f);
}

// ---------------------------------------------------------------------------
extern "C" void kernel_launch(void* const* d_in, const int* in_sizes, int n_in,
                              void* d_out, int out_size)
{
    const float* X  = (const float*)d_in[0];
    const float* Wq = (const float*)d_in[1];
    const float* Wk = (const float*)d_in[2];
    const float* Wv = (const float*)d_in[3];
    float* Out = (float*)d_out;

    qkv_kernel<<<dim3(D / 128, (BATCH * SEQ) / 128, 3), 256>>>(X, Wq, Wk, Wv);
    scores_kernel<<<dim3(SEQ / 128, SEQ / 128, BATCH), 256>>>();
    softmax_kernel<<<dim3(SEQ, BATCH), 256>>>();
    pv_kernel<<<dim3(D / 128, SEQ / 128, BATCH), 256>>>(Out);
}

// round 4
// speedup vs baseline: 2.3849x; 1.1005x over previous
#include <cuda_runtime.h>
#include <cuda_bf16.h>
#include <math.h>
#include <stdint.h>

#define D     768
#define SEQ   4096
#define BATCH 4
#define NTOK  (BATCH * SEQ)
#define SCALE 0.03608439182435161f  // 1/sqrt(768)

typedef __nv_bfloat16 bf16;

// ---------------------------------------------------------------------------
// Device-global scratch (no allocation allowed)
// ---------------------------------------------------------------------------
__device__ __align__(256) bf16 g_Xh[NTOK * D], g_Xl[NTOK * D];
__device__ __align__(256) bf16 g_Wh[3 * D * D], g_Wl[3 * D * D];
__device__ __align__(256) bf16 g_Qh[NTOK * D], g_Ql[NTOK * D];
__device__ __align__(256) bf16 g_Kh[NTOK * D], g_Kl[NTOK * D];
__device__ __align__(256) bf16 g_Vth[NTOK * D], g_Vtl[NTOK * D];  // [b][d][seq]
__device__ float g_S[(size_t)BATCH * SEQ * SEQ];                   // raw scaled scores
__device__ __align__(256) bf16 g_Ph[(size_t)BATCH * SEQ * SEQ];
__device__ __align__(256) bf16 g_Pl[(size_t)BATCH * SEQ * SEQ];

// smem tiling: 128 rows x 32 bf16 cols, padded stride 40 (conflict-free ldmatrix)
#define LSTR    40
#define TILE_B  (128 * LSTR * 2)     // 10240 B per tile
#define STAGE_B (4 * TILE_B)         // Ah|Al|Bh|Bl = 40960 B
#define DYN_SMEM (2 * STAGE_B)       // 81920 B (double buffer)

// ---------------------------------------------------------------------------
// PTX helpers
// ---------------------------------------------------------------------------
__device__ __forceinline__ uint32_t smem_u32(const void* p) {
    uint32_t a;
    asm("{ .reg .u64 t; cvta.to.shared.u64 t, %1; cvt.u32.u64 %0, t; }" : "=r"(a) : "l"(p));
    return a;
}
__device__ __forceinline__ void ldsm4(uint32_t r[4], uint32_t addr) {
    asm volatile("ldmatrix.sync.aligned.m8n8.x4.shared.b16 {%0,%1,%2,%3}, [%4];"
                 : "=r"(r[0]), "=r"(r[1]), "=r"(r[2]), "=r"(r[3]) : "r"(addr));
}
__device__ __forceinline__ void mma16816(float c[4], const uint32_t a[4],
                                         uint32_t b0, uint32_t b1) {
    asm volatile(
        "mma.sync.aligned.m16n8k16.row.col.f32.bf16.bf16.f32 "
        "{%0,%1,%2,%3}, {%4,%5,%6,%7}, {%8,%9}, {%0,%1,%2,%3};"
        : "+f"(c[0]), "+f"(c[1]), "+f"(c[2]), "+f"(c[3])
        : "r"(a[0]), "r"(a[1]), "r"(a[2]), "r"(a[3]), "r"(b0), "r"(b1));
}
#define CP16(dst, src) asm volatile("cp.async.cg.shared.global [%0], [%1], 16;" :: "r"(dst), "l"(src) : "memory")
#define CP_COMMIT()    asm volatile("cp.async.commit_group;" ::: "memory")
#define CP_WAIT0()     asm volatile("cp.async.wait_group 0;" ::: "memory")
#define CP_WAIT1()     asm volatile("cp.async.wait_group 1;" ::: "memory")

__device__ __forceinline__ unsigned short bfu(bf16 x) {
    return *reinterpret_cast<unsigned short*>(&x);
}

// ---------------------------------------------------------------------------
// Load one K-chunk (Ah,Al,Bh,Bl tiles of 128x32 bf16) into a stage
// ---------------------------------------------------------------------------
__device__ __forceinline__ void load_chunk(
    uint32_t stage,
    const bf16* __restrict__ Ah, const bf16* __restrict__ Al, int lda,
    const bf16* __restrict__ Bh, const bf16* __restrict__ Bl, int ldb, int k0)
{
    const int t   = threadIdx.x;
    const int seg = t & 3;        // 16B segment (8 bf16) within 64B row
    const int r0  = t >> 2;       // 0..63
    #pragma unroll
    for (int i = 0; i < 2; i++) {
        const int row = r0 + i * 64;
        const uint32_t so = (uint32_t)(row * LSTR + seg * 8) * 2;
        const size_t ga = (size_t)row * lda + k0 + seg * 8;
        const size_t gb = (size_t)row * ldb + k0 + seg * 8;
        CP16(stage + 0 * TILE_B + so, Ah + ga);
        CP16(stage + 1 * TILE_B + so, Al + ga);
        CP16(stage + 2 * TILE_B + so, Bh + gb);
        CP16(stage + 3 * TILE_B + so, Bl + gb);
    }
}

// ---------------------------------------------------------------------------
// Compute one K-chunk (K=32) from a stage into acc[2][8][4]
// ---------------------------------------------------------------------------
__device__ __forceinline__ void compute_chunk(
    uint32_t stage, const uint32_t offA[2], const uint32_t offB[4],
    float acc[2][8][4])
{
    const uint32_t aH = stage, aL = stage + TILE_B;
    const uint32_t bH = stage + 2 * TILE_B, bL = stage + 3 * TILE_B;
    #pragma unroll
    for (int kk = 0; kk < 32; kk += 16) {
        uint32_t afh[2][4], afl[2][4];
        ldsm4(afh[0], aH + offA[0] + kk * 2);
        ldsm4(afh[1], aH + offA[1] + kk * 2);
        ldsm4(afl[0], aL + offA[0] + kk * 2);
        ldsm4(afl[1], aL + offA[1] + kk * 2);
        #pragma unroll
        for (int g = 0; g < 4; g++) {
            uint32_t bh[4], bl[4];
            ldsm4(bh, bH + offB[g] + kk * 2);
            ldsm4(bl, bL + offB[g] + kk * 2);
            #pragma unroll
            for (int mt = 0; mt < 2; mt++) {
                #pragma unroll
                for (int nt = 0; nt < 2; nt++) {
                    float* c = acc[mt][g * 2 + nt];
                    mma16816(c, afh[mt], bh[nt * 2], bh[nt * 2 + 1]); // hi*hi
                    mma16816(c, afh[mt], bl[nt * 2], bl[nt * 2 + 1]); // hi*lo
                    mma16816(c, afl[mt], bh[nt * 2], bh[nt * 2 + 1]); // lo*hi
                }
            }
        }
    }
}

// ---------------------------------------------------------------------------
// GEMM driver: acc = A[128,K] * B[128,K]^T, double-buffered cp.async pipeline
// ---------------------------------------------------------------------------
__device__ __forceinline__ void gemm_run(
    const bf16* __restrict__ Ah, const bf16* __restrict__ Al, int lda,
    const bf16* __restrict__ Bh, const bf16* __restrict__ Bl, int ldb,
    int nchunks, float acc[2][8][4])
{
    extern __shared__ char dsm[];
    const uint32_t base = smem_u32(dsm);

    const int lane = threadIdx.x & 31;
    const int warp = threadIdx.x >> 5;
    const int wm = warp >> 1, wn = warp & 1;
    const int rowA = ((lane >> 3) & 1) * 8 + (lane & 7);
    const int colA = (lane >> 4) * 8;
    const int rowB = (lane >> 4) * 8 + (lane & 7);
    const int colB = ((lane >> 3) & 1) * 8;

    uint32_t offA[2], offB[4];
    #pragma unroll
    for (int mt = 0; mt < 2; mt++)
        offA[mt] = ((wm * 32 + mt * 16 + rowA) * LSTR + colA) * 2;
    #pragma unroll
    for (int g = 0; g < 4; g++)
        offB[g] = ((wn * 64 + g * 16 + rowB) * LSTR + colB) * 2;

    load_chunk(base, Ah, Al, lda, Bh, Bl, ldb, 0);
    CP_COMMIT();

    for (int c = 0; c < nchunks; c++) {
        if (c + 1 < nchunks) {
            load_chunk(base + ((c + 1) & 1) * STAGE_B, Ah, Al, lda, Bh, Bl, ldb,
                       (c + 1) * 32);
            CP_COMMIT();
            CP_WAIT1();
        } else {
            CP_WAIT0();
        }
        __syncthreads();
        compute_chunk(base + (c & 1) * STAGE_B, offA, offB, acc);
        __syncthreads();
    }
}

// ---------------------------------------------------------------------------
// Epilogues. acc element (mt,j,e): r = wm*32+mt*16+(lane>>2)+(e>=2?8:0),
//                                  c = wn*64+j*8+(lane&3)*2+(e&1)
// ---------------------------------------------------------------------------
__device__ __forceinline__ void store_f32(
    float* __restrict__ C, size_t ldc, int row0, int col0,
    const float acc[2][8][4], float scale)
{
    const int lane = threadIdx.x & 31;
    const int warp = threadIdx.x >> 5;
    const int wm = warp >> 1, wn = warp & 1;
    #pragma unroll
    for (int mt = 0; mt < 2; mt++) {
        const int r = row0 + wm * 32 + mt * 16 + (lane >> 2);
        #pragma unroll
        for (int j = 0; j < 8; j++) {
            const int c = col0 + wn * 64 + j * 8 + (lane & 3) * 2;
            *(float2*)(C + (size_t)r * ldc + c) =
                make_float2(acc[mt][j][0] * scale, acc[mt][j][1] * scale);
            *(float2*)(C + (size_t)(r + 8) * ldc + c) =
                make_float2(acc[mt][j][2] * scale, acc[mt][j][3] * scale);
        }
    }
}

__device__ __forceinline__ uint32_t split_pack(float v0, float v1, uint32_t& lo) {
    bf16 h0 = __float2bfloat16_rn(v0), h1 = __float2bfloat16_rn(v1);
    bf16 l0 = __float2bfloat16_rn(v0 - __bfloat162float(h0));
    bf16 l1 = __float2bfloat16_rn(v1 - __bfloat162float(h1));
    lo = (uint32_t)bfu(l0) | ((uint32_t)bfu(l1) << 16);
    return (uint32_t)bfu(h0) | ((uint32_t)bfu(h1) << 16);
}

__device__ __forceinline__ void store_split(
    bf16* __restrict__ Hh, bf16* __restrict__ Hl, size_t ldc,
    int row0, int col0, const float acc[2][8][4])
{
    const int lane = threadIdx.x & 31;
    const int warp = threadIdx.x >> 5;
    const int wm = warp >> 1, wn = warp & 1;
    #pragma unroll
    for (int mt = 0; mt < 2; mt++) {
        const int r = row0 + wm * 32 + mt * 16 + (lane >> 2);
        #pragma unroll
        for (int j = 0; j < 8; j++) {
            const int c = col0 + wn * 64 + j * 8 + (lane & 3) * 2;
            uint32_t lo0, lo1;
            uint32_t hi0 = split_pack(acc[mt][j][0], acc[mt][j][1], lo0);
            uint32_t hi1 = split_pack(acc[mt][j][2], acc[mt][j][3], lo1);
            *(uint32_t*)(Hh + (size_t)r * ldc + c)       = hi0;
            *(uint32_t*)(Hl + (size_t)r * ldc + c)       = lo0;
            *(uint32_t*)(Hh + (size_t)(r + 8) * ldc + c) = hi1;
            *(uint32_t*)(Hl + (size_t)(r + 8) * ldc + c) = lo1;
        }
    }
}

// Transposed V store via smem (one plane at a time: 128*136*2 = 34816 B)
#define VT_STRIDE 136
__device__ __forceinline__ void store_vt(int row0, int col0, const float acc[2][8][4])
{
    extern __shared__ char dsm[];
    unsigned short* sp = (unsigned short*)dsm;
    const int tid  = threadIdx.x;
    const int lane = tid & 31;
    const int warp = tid >> 5;
    const int wm = warp >> 1, wn = warp & 1;

    const int b   = row0 >> 12;
    const int rin = row0 & (SEQ - 1);
    const int d    = tid >> 1;
    const int ks   = (tid & 1) * 64;
    const size_t off = (size_t)b * D * SEQ + (size_t)(col0 + d) * SEQ + rin + ks;

    #pragma unroll
    for (int plane = 0; plane < 2; plane++) {
        __syncthreads();
        #pragma unroll
        for (int mt = 0; mt < 2; mt++) {
            const int r = wm * 32 + mt * 16 + (lane >> 2);
            #pragma unroll
            for (int j = 0; j < 8; j++) {
                const int c = wn * 64 + j * 8 + (lane & 3) * 2;
                #pragma unroll
                for (int e = 0; e < 4; e++) {
                    float v = acc[mt][j][e];
                    bf16 h = __float2bfloat16_rn(v);
                    bf16 w = plane ? __float2bfloat16_rn(v - __bfloat162float(h)) : h;
                    sp[(r + (e >> 1) * 8) * VT_STRIDE + c + (e & 1)] = bfu(w);
                }
            }
        }
        __syncthreads();
        bf16* dst = (plane ? g_Vtl : g_Vth) + off;
        #pragma unroll
        for (int g = 0; g < 8; g++) {
            uint32_t w[4];
            #pragma unroll
            for (int h = 0; h < 4; h++) {
                uint32_t a0 = sp[(ks + g * 8 + h * 2) * VT_STRIDE + d];
                uint32_t a1 = sp[(ks + g * 8 + h * 2 + 1) * VT_STRIDE + d];
                w[h] = a0 | (a1 << 16);
            }
            *(uint4*)(dst + g * 8) = make_uint4(w[0], w[1], w[2], w[3]);
        }
    }
}

// ---------------------------------------------------------------------------
// Kernels
// ---------------------------------------------------------------------------
__global__ void __launch_bounds__(256) split_kernel(const float* __restrict__ src,
                                                    bf16* __restrict__ h,
                                                    bf16* __restrict__ l, int n)
{
    int i = (blockIdx.x * 256 + threadIdx.x) * 4;
    if (i >= n) return;
    float4 v = *(const float4*)(src + i);
    uint32_t lo0, lo1;
    uint32_t hi0 = split_pack(v.x, v.y, lo0);
    uint32_t hi1 = split_pack(v.z, v.w, lo1);
    *(uint2*)(h + i) = make_uint2(hi0, hi1);
    *(uint2*)(l + i) = make_uint2(lo0, lo1);
}

__global__ void __launch_bounds__(256, 2) qkv_mm()
{
    const int z    = blockIdx.z;
    const int row0 = blockIdx.y * 128;
    const int col0 = blockIdx.x * 128;
    const bf16* wh = g_Wh + (size_t)z * D * D + (size_t)col0 * D;
    const bf16* wl = g_Wl + (size_t)z * D * D + (size_t)col0 * D;

    float acc[2][8][4] = {};
    gemm_run(g_Xh + (size_t)row0 * D, g_Xl + (size_t)row0 * D, D,
             wh, wl, D, D / 32, acc);

    if (z == 0)      store_split(g_Qh, g_Ql, D, row0, col0, acc);
    else if (z == 1) store_split(g_Kh, g_Kl, D, row0, col0, acc);
    else             store_vt(row0, col0, acc);
}

__global__ void __launch_bounds__(256, 2) scores_mm()
{
    const int t = blockIdx.x;
    int by = (int)((sqrtf(8.0f * t + 1.0f) - 1.0f) * 0.5f);
    while ((by + 1) * (by + 2) / 2 <= t) by++;
    while (by * (by + 1) / 2 > t) by--;
    const int bx = t - by * (by + 1) / 2;
    const int b  = blockIdx.y;
    const int row0 = by * 128, col0 = bx * 128;
    const size_t qoff = (size_t)b * SEQ * D;

    float acc[2][8][4] = {};
    gemm_run(g_Qh + qoff + (size_t)row0 * D, g_Ql + qoff + (size_t)row0 * D, D,
             g_Kh + qoff + (size_t)col0 * D, g_Kl + qoff + (size_t)col0 * D, D,
             D / 32, acc);
    store_f32(g_S + (size_t)b * SEQ * SEQ, SEQ, row0, col0, acc, SCALE);
}

__global__ void __launch_bounds__(256) softmax_kernel()
{
    const int q = blockIdx.x;
    const int b = blockIdx.y;
    const float* row = g_S + (size_t)b * SEQ * SEQ + (size_t)q * SEQ;
    const int len  = q + 1;
    const int wlen = ((q >> 7) + 1) << 7;
    const int tid  = threadIdx.x;
    __shared__ float red[256];

    float m = -INFINITY;
    for (int i = tid; i < len; i += 256) m = fmaxf(m, row[i]);
    red[tid] = m; __syncthreads();
    #pragma unroll
    for (int s = 128; s > 0; s >>= 1) {
        if (tid < s) red[tid] = fmaxf(red[tid], red[tid + s]);
        __syncthreads();
    }
    m = red[0]; __syncthreads();

    float sum = 0.0f;
    for (int i = tid; i < len; i += 256) sum += __expf(row[i] - m);
    red[tid] = sum; __syncthreads();
    #pragma unroll
    for (int s = 128; s > 0; s >>= 1) {
        if (tid < s) red[tid] += red[tid + s];
        __syncthreads();
    }
    const float inv = 1.0f / red[0];
    __syncthreads();

    bf16* ph = g_Ph + (size_t)b * SEQ * SEQ + (size_t)q * SEQ;
    bf16* pl = g_Pl + (size_t)b * SEQ * SEQ + (size_t)q * SEQ;
    for (int i = tid; i < wlen; i += 256) {
        bf16 h, l;
        if (i < len) {
            float p = __expf(row[i] - m) * inv;
            h = __float2bfloat16_rn(p);
            l = __float2bfloat16_rn(p - __bfloat162float(h));
        } else {
            h = __float2bfloat16_rn(0.0f);
            l = h;
        }
        ph[i] = h;
        pl[i] = l;
    }
}

__global__ void __launch_bounds__(256, 2) pv_mm(float* __restrict__ Out)
{
    const int b    = blockIdx.z;
    const int by   = blockIdx.y;
    const int row0 = by * 128;
    const int col0 = blockIdx.x * 128;
    const int nchunks = (by + 1) * 4;   // Klim / 32

    const size_t poff = (size_t)b * SEQ * SEQ + (size_t)row0 * SEQ;
    const size_t voff = (size_t)b * D * SEQ + (size_t)col0 * SEQ;

    float acc[2][8][4] = {};
    gemm_run(g_Ph + poff, g_Pl + poff, SEQ,
             g_Vth + voff, g_Vtl + voff, SEQ, nchunks, acc);
    store_f32(Out + (size_t)b * SEQ * D, D, row0, col0, acc, 1.0f);
}

// ---------------------------------------------------------------------------
extern "C" void kernel_launch(void* const* d_in, const int* in_sizes, int n_in,
                              void* d_out, int out_size)
{
    const float* X  = (const float*)d_in[0];
    const float* Wq = (const float*)d_in[1];
    const float* Wk = (const float*)d_in[2];
    const float* Wv = (const float*)d_in[3];
    float* Out = (float*)d_out;

    cudaFuncSetAttribute(qkv_mm,    cudaFuncAttributeMaxDynamicSharedMemorySize, DYN_SMEM);
    cudaFuncSetAttribute(scores_mm, cudaFuncAttributeMaxDynamicSharedMemorySize, DYN_SMEM);
    cudaFuncSetAttribute(pv_mm,     cudaFuncAttributeMaxDynamicSharedMemorySize, DYN_SMEM);

    bf16 *xh, *xl, *wh, *wl;
    cudaGetSymbolAddress((void**)&xh, g_Xh);
    cudaGetSymbolAddress((void**)&xl, g_Xl);
    cudaGetSymbolAddress((void**)&wh, g_Wh);
    cudaGetSymbolAddress((void**)&wl, g_Wl);

    split_kernel<<<(NTOK * D) / 1024, 256>>>(X, xh, xl, NTOK * D);
    split_kernel<<<(D * D) / 1024, 256>>>(Wq, wh + 0 * D * D, wl + 0 * D * D, D * D);
    split_kernel<<<(D * D) / 1024, 256>>>(Wk, wh + 1 * D * D, wl + 1 * D * D, D * D);
    split_kernel<<<(D * D) / 1024, 256>>>(Wv, wh + 2 * D * D, wl + 2 * D * D, D * D);

    qkv_mm<<<dim3(D / 128, NTOK / 128, 3), 256, DYN_SMEM>>>();
    scores_mm<<<dim3(528, BATCH), 256, DYN_SMEM>>>();
    softmax_kernel<<<dim3(SEQ, BATCH), 256>>>();
    pv_mm<<<dim3(D / 128, SEQ / 128, BATCH), 256, DYN_SMEM>>>(Out);
}